// round 1
// baseline (speedup 1.0000x reference)
#include <cuda_runtime.h>
#include <cstdint>

#define VSZ 10000   // vocab
#define QSZ 1000    // P * LM1
#define KD  300     // embedding dim D
#define BB  256     // batch
#define TT  128     // max doc len
#define PP  200     // patterns

// 40 MB scratch table, layout [v][q] so a token's row (1000 floats) is contiguous.
__device__ __align__(16) float g_table[(size_t)VSZ * QSZ];

// ---------------------------------------------------------------------------
// Kernel 1: g_table[v][q] = sum_k emb[k][v] * diags[q][k] + bias[q]
// Tile: 128 (v) x 128 (q), K-tile 8, 256 threads, 8x8 accumulators/thread.
// ---------------------------------------------------------------------------
__global__ void __launch_bounds__(256) gemm_kernel(const float* __restrict__ emb,
                                                   const float* __restrict__ diags,
                                                   const float* __restrict__ bias)
{
    __shared__ float As[2][8][128];   // [k][v]
    __shared__ float Bs[2][8][132];   // [k][q], padded to kill STS conflicts

    const int v0  = blockIdx.x * 128;
    const int q0  = blockIdx.y * 128;
    const int tid = threadIdx.x;
    const int tv  = tid & 15;     // v sub-row group: rows tv*8 .. tv*8+7
    const int tq  = tid >> 4;     // q sub-col group: cols tq*8 .. tq*8+7

    float acc[8][8];
#pragma unroll
    for (int i = 0; i < 8; i++)
#pragma unroll
        for (int j = 0; j < 8; j++) acc[i][j] = 0.f;

    auto loadA = [&](int bf, int k0) {
#pragma unroll
        for (int i = 0; i < 4; i++) {
            int l = tid + i * 256;
            int k = l >> 7, v = l & 127;
            int gk = k0 + k, gv = v0 + v;
            float val = 0.f;
            if (gk < KD && gv < VSZ) val = emb[gk * VSZ + gv];   // coalesced in v
            As[bf][k][v] = val;
        }
    };
    auto loadB = [&](int bf, int k0) {
#pragma unroll
        for (int i = 0; i < 4; i++) {
            int l = tid + i * 256;
            int k = l & 7, q = l >> 3;
            int gk = k0 + k, gq = q0 + q;
            float val = 0.f;
            if (gk < KD && gq < QSZ) val = diags[gq * KD + gk];  // 32B sectors, L2-resident
            Bs[bf][k][q] = val;
        }
    };

    loadA(0, 0);
    loadB(0, 0);
    __syncthreads();

    const int nk = (KD + 7) / 8;   // 38
    for (int kt = 0; kt < nk; kt++) {
        int cur = kt & 1, nxt = cur ^ 1;
        if (kt + 1 < nk) { loadA(nxt, (kt + 1) * 8); loadB(nxt, (kt + 1) * 8); }
#pragma unroll
        for (int kk = 0; kk < 8; kk++) {
            float a[8], bq[8];
#pragma unroll
            for (int i = 0; i < 8; i++) a[i]  = As[cur][kk][tv * 8 + i];
#pragma unroll
            for (int j = 0; j < 8; j++) bq[j] = Bs[cur][kk][tq * 8 + j];
#pragma unroll
            for (int i = 0; i < 8; i++)
#pragma unroll
                for (int j = 0; j < 8; j++)
                    acc[i][j] += a[i] * bq[j];
        }
        __syncthreads();
    }

    // Epilogue: + bias, vectorized float4 stores. 10000 % 8 == 0 and 1000 % 8 == 0,
    // so whole 8-wide groups are either fully valid or fully invalid.
    const int qb = q0 + tq * 8;
    const int vb = v0 + tv * 8;
    if (qb < QSZ) {
        float bv[8];
#pragma unroll
        for (int j = 0; j < 8; j++) bv[j] = bias[qb + j];
#pragma unroll
        for (int i = 0; i < 8; i++) {
            int gv = vb + i;
            if (gv < VSZ) {
                float4* dst = reinterpret_cast<float4*>(&g_table[(size_t)gv * QSZ + qb]);
                dst[0] = make_float4(acc[i][0] + bv[0], acc[i][1] + bv[1],
                                     acc[i][2] + bv[2], acc[i][3] + bv[3]);
                dst[1] = make_float4(acc[i][4] + bv[4], acc[i][5] + bv[5],
                                     acc[i][6] + bv[6], acc[i][7] + bv[7]);
            }
        }
    }
}

// ---------------------------------------------------------------------------
// Kernel 2: one block per batch row. cp.async 4-stage pipeline streams the
// token's table row (4000 B) into smem; thread p (<200) runs the 5-state
// Viterbi chain in registers; fused mean/binarize/linear epilogue.
// ---------------------------------------------------------------------------
__global__ void __launch_bounds__(256) scan_kernel(const int* __restrict__ docs,
                                                   const int* __restrict__ doc_lens,
                                                   const int* __restrict__ end_states,
                                                   const float* __restrict__ wild,
                                                   const float* __restrict__ lin_w,
                                                   const float* __restrict__ lin_b,
                                                   float* __restrict__ out)
{
    __shared__ __align__(16) float buf[4][1000];
    __shared__ int   toks[TT];
    __shared__ float wsum[8];
    __shared__ float wsum2[2][8];
    __shared__ float s_mean;

    const int b   = blockIdx.x;
    const int tid = threadIdx.x;
    const int len = doc_lens[b];

    if (tid < TT) toks[tid] = docs[b * TT + tid];

    const bool act = tid < PP;
    float w0 = 0.f, w1 = 0.f, w2 = 0.f, w3 = 0.f, w4 = 0.f;
    int e = 2;
    if (act) {
        w0 = wild[tid * 5 + 0];
        w1 = wild[tid * 5 + 1];
        w2 = wild[tid * 5 + 2];
        w3 = wild[tid * 5 + 3];
        w4 = wild[tid * 5 + 4];
        e  = end_states[tid];
    }
    __syncthreads();

    const float NEG = __int_as_float(0xff800000);   // -inf
    float h1 = NEG, h2 = NEG, h3 = NEG, h4 = NEG, h5 = NEG, sc = NEG;

    const uint32_t sbase = (uint32_t)__cvta_generic_to_shared(buf);

    // Prologue: len >= 8 > 4 always, so 4 full stages.
#pragma unroll
    for (int s = 0; s < 4; s++) {
        if (tid < 250) {
            const float* g = g_table + (size_t)toks[s] * QSZ + tid * 4;
            uint32_t d = sbase + s * 4000 + tid * 16;
            asm volatile("cp.async.cg.shared.global [%0], [%1], 16;" :: "r"(d), "l"(g));
        }
        asm volatile("cp.async.commit_group;");
    }

    for (int t = 0; t < len; t++) {
        asm volatile("cp.async.wait_group 3;");
        __syncthreads();
        if (act) {
            const float* r = &buf[t & 3][tid * 5];
            float m0 = fmaxf(r[0], w0);
            float m1 = fmaxf(r[1], w1);
            float m2 = fmaxf(r[2], w2);
            float m3 = fmaxf(r[3], w3);
            float m4 = fmaxf(r[4], w4);
            h5 = h4 + m4;          // uses OLD h4..h1 (sequenced descending)
            h4 = h3 + m3;
            h3 = h2 + m2;
            h2 = h1 + m1;
            h1 = m0;               // restart state contributes 0
            float ev = (e == 2) ? h2 : (e == 3) ? h3 : (e == 4) ? h4 : h5;
            sc = fmaxf(sc, ev);
        }
        __syncthreads();
        int tn = t + 4;
        if (tn < len && tid < 250) {
            const float* g = g_table + (size_t)toks[tn] * QSZ + tid * 4;
            uint32_t d = sbase + (tn & 3) * 4000 + tid * 16;
            asm volatile("cp.async.cg.shared.global [%0], [%1], 16;" :: "r"(d), "l"(g));
        }
        asm volatile("cp.async.commit_group;");   // empty groups keep the count consistent
    }

    // ---- Epilogue: LN+binarize collapses to (sc > mean); then 2-wide linear ----
    const int lane = tid & 31, warp = tid >> 5;

    float x = act ? sc : 0.f;
#pragma unroll
    for (int o = 16; o; o >>= 1) x += __shfl_down_sync(0xffffffffu, x, o);
    if (lane == 0) wsum[warp] = x;
    __syncthreads();
    if (tid == 0) {
        float tot = 0.f;
#pragma unroll
        for (int i = 0; i < 8; i++) tot += wsum[i];
        s_mean = tot / 200.f;
    }
    __syncthreads();
    const float mean = s_mean;

    float c0 = 0.f, c1 = 0.f;
    if (act && sc > mean) {       // binarized == 1
        c0 = lin_w[tid];          // lin_w is (C=2, P=200) row-major
        c1 = lin_w[PP + tid];
    }
#pragma unroll
    for (int o = 16; o; o >>= 1) {
        c0 += __shfl_down_sync(0xffffffffu, c0, o);
        c1 += __shfl_down_sync(0xffffffffu, c1, o);
    }
    if (lane == 0) { wsum2[0][warp] = c0; wsum2[1][warp] = c1; }
    __syncthreads();
    if (tid == 0) {
        float t0 = 0.f, t1 = 0.f;
#pragma unroll
        for (int i = 0; i < 8; i++) { t0 += wsum2[0][i]; t1 += wsum2[1][i]; }
        out[b * 2 + 0] = t0 + lin_b[0];
        out[b * 2 + 1] = t1 + lin_b[1];
    }
}

// ---------------------------------------------------------------------------
extern "C" void kernel_launch(void* const* d_in, const int* in_sizes, int n_in,
                              void* d_out, int out_size)
{
    const int*   docs       = (const int*)  d_in[0];
    const int*   doc_lens   = (const int*)  d_in[1];
    const int*   end_states = (const int*)  d_in[2];
    const float* emb        = (const float*)d_in[3];
    const float* diags      = (const float*)d_in[4];
    const float* bias       = (const float*)d_in[5];
    const float* wild       = (const float*)d_in[6];
    const float* lin_w      = (const float*)d_in[7];
    const float* lin_b      = (const float*)d_in[8];
    float* out = (float*)d_out;

    dim3 ggrid((VSZ + 127) / 128, (QSZ + 127) / 128);   // 79 x 8
    gemm_kernel<<<ggrid, 256>>>(emb, diags, bias);
    scan_kernel<<<BB, 256>>>(docs, doc_lens, end_states, wild, lin_w, lin_b, out);
}

// round 7
// speedup vs baseline: 1.4009x; 1.4009x over previous
#include <cuda_runtime.h>
#include <cstdint>

#define VSZ 10000   // vocab
#define KD  300     // embedding dim D
#define BB  256     // batch
#define TT  128     // max doc len
#define PP  200     // patterns

#define QP   768    // packed q columns (700 real, padded)
#define KPAD 304    // K padded to 38*8
#define NKT  38     // k-tiles of 8
#define VT   79     // v tiles of 128 (9984..10111 padded)
#define JT   6      // j tiles of 128

// Device scratch (no allocation allowed)
__device__ __align__(16) float g_table[(size_t)VSZ * QP];     // 30.7 MB, [v][j]
__device__ __align__(16) float g_Bpack[(size_t)KPAD * QP];    // 0.93 MB, [k][j]
__device__ __align__(16) float g_biasp[QP];

__device__ __forceinline__ uint32_t smem_u32(const void* p) {
    uint32_t a;
    asm("{ .reg .u64 t; cvta.to.shared.u64 t, %1; cvt.u32.u64 %0, t; }" : "=r"(a) : "l"(p));
    return a;
}

// packed j (0..699) -> source q = p*5 + l   (end_states = repeat([2,3,4,5],50))
__device__ __forceinline__ int packed_to_src(int j) {
    if (j < 100) return (j >> 1) * 5 + (j & 1);
    if (j < 250) { int r = j - 100; return (50  + r / 3) * 5 + r % 3; }
    if (j < 450) { int r = j - 250; return (100 + r / 4) * 5 + r % 4; }
    { int r = j - 450; return (150 + r / 5) * 5 + r % 5; }
}

// ---------------------------------------------------------------------------
// pack: g_Bpack[k][j] = diags[src(j)][k] (zero-padded), g_biasp[j] = bias[src(j)]
// ---------------------------------------------------------------------------
__global__ void __launch_bounds__(256) pack_kernel(const float* __restrict__ diags,
                                                   const float* __restrict__ bias)
{
    int idx = blockIdx.x * 256 + threadIdx.x;
    if (idx < KPAD * QP) {
        int k = idx / QP, j = idx % QP;
        g_Bpack[idx] = (k < KD && j < 700) ? diags[packed_to_src(j) * KD + k] : 0.f;
    }
    if (idx < QP)
        g_biasp[idx] = (idx < 700) ? bias[packed_to_src(idx)] : 0.f;
}

// ---------------------------------------------------------------------------
// GEMM (fp32 exact, f32x2-packed FMA):
//   g_table[v][j] = sum_k emb[k][v] * Bpack[k][j] + biasp[j]
// CTA tile 128(v) x 128(j), 256 thr, 8x8 per thread (acc pairs along j).
// Double-buffered cp.async, k-step 8.
// ---------------------------------------------------------------------------
__global__ void __launch_bounds__(256, 2) gemm_kernel(const float* __restrict__ emb)
{
    __shared__ __align__(16) float As[2][8][128];   // [k][v]
    __shared__ __align__(16) float Bs[2][8][128];   // [k][j]

    const int tid = threadIdx.x;
    const int tv  = tid & 15;      // row group: rows tv*8 .. tv*8+7
    const int tq  = tid >> 4;      // col group: cols tq*8 .. tq*8+7
    const int j0  = blockIdx.x * 128;
    const int v0  = blockIdx.y * 128;

    const uint32_t sbA = smem_u32(As);
    const uint32_t sbB = smem_u32(Bs);

    // copy k-tile kt into buffer bf: each thread moves one 16B of A and of B
    const int cl = tid * 4;
    const int ck = cl >> 7;          // 0..7
    const int cv = cl & 127;
    auto issue_copy = [&](int kt, int bf) {
        int gk = kt * 8 + ck;
        int gv = v0 + cv;
        // A from emb[k][v] (guard k<KD, v<VSZ via src-size 0 => zero-fill)
        uint32_t pa = (gk < KD && gv < VSZ) ? 16u : 0u;
        const float* ga = emb + (size_t)(pa ? gk : 0) * VSZ + (pa ? gv : 0);
        uint32_t da = sbA + (bf * 1024 + ck * 128 + cv) * 4;
        asm volatile("cp.async.cg.shared.global [%0], [%1], 16, %2;"
                     :: "r"(da), "l"(ga), "r"(pa));
        // B from g_Bpack[k][j]  (rows < KPAD always valid, zero-padded)
        const float* gb = g_Bpack + (size_t)gk * QP + j0 + cv;
        uint32_t db = sbB + (bf * 1024 + ck * 128 + cv) * 4;
        asm volatile("cp.async.cg.shared.global [%0], [%1], 16;"
                     :: "r"(db), "l"(gb));
    };

    unsigned long long acc[8][4];
#pragma unroll
    for (int r = 0; r < 8; r++)
#pragma unroll
        for (int jp = 0; jp < 4; jp++) acc[r][jp] = 0ull;

    issue_copy(0, 0);
    asm volatile("cp.async.commit_group;");

    for (int kt = 0; kt < NKT; kt++) {
        if (kt + 1 < NKT) issue_copy(kt + 1, (kt + 1) & 1);
        asm volatile("cp.async.commit_group;");
        asm volatile("cp.async.wait_group 1;");
        __syncthreads();

        const int bf = kt & 1;
#pragma unroll
        for (int kk = 0; kk < 8; kk++) {
            // A scalars (8 rows) -> splats
            const uint4* ap = reinterpret_cast<const uint4*>(&As[bf][kk][tv * 8]);
            uint4 a01 = ap[0], a23 = ap[1];
            unsigned long long as_[8];
            asm("mov.b64 %0, {%1, %1};" : "=l"(as_[0]) : "r"(a01.x));
            asm("mov.b64 %0, {%1, %1};" : "=l"(as_[1]) : "r"(a01.y));
            asm("mov.b64 %0, {%1, %1};" : "=l"(as_[2]) : "r"(a01.z));
            asm("mov.b64 %0, {%1, %1};" : "=l"(as_[3]) : "r"(a01.w));
            asm("mov.b64 %0, {%1, %1};" : "=l"(as_[4]) : "r"(a23.x));
            asm("mov.b64 %0, {%1, %1};" : "=l"(as_[5]) : "r"(a23.y));
            asm("mov.b64 %0, {%1, %1};" : "=l"(as_[6]) : "r"(a23.z));
            asm("mov.b64 %0, {%1, %1};" : "=l"(as_[7]) : "r"(a23.w));
            // B pairs (4 x f32x2) direct 64-bit loads
            const unsigned long long* bp =
                reinterpret_cast<const unsigned long long*>(&Bs[bf][kk][tq * 8]);
            unsigned long long b0 = bp[0], b1 = bp[1], b2 = bp[2], b3 = bp[3];
#pragma unroll
            for (int r = 0; r < 8; r++) {
                asm("fma.rn.f32x2 %0, %1, %2, %0;" : "+l"(acc[r][0]) : "l"(as_[r]), "l"(b0));
                asm("fma.rn.f32x2 %0, %1, %2, %0;" : "+l"(acc[r][1]) : "l"(as_[r]), "l"(b1));
                asm("fma.rn.f32x2 %0, %1, %2, %0;" : "+l"(acc[r][2]) : "l"(as_[r]), "l"(b2));
                asm("fma.rn.f32x2 %0, %1, %2, %0;" : "+l"(acc[r][3]) : "l"(as_[r]), "l"(b3));
            }
        }
        __syncthreads();
    }

    // Epilogue: unpack, add bias, float4 stores
    const int jb = j0 + tq * 8;
    float bv[8];
#pragma unroll
    for (int j = 0; j < 8; j++) bv[j] = g_biasp[jb + j];

#pragma unroll
    for (int r = 0; r < 8; r++) {
        int v = v0 + tv * 8 + r;
        if (v < VSZ) {
            float f[8];
#pragma unroll
            for (int jp = 0; jp < 4; jp++)
                asm("mov.b64 {%0, %1}, %2;" : "=f"(f[jp * 2]), "=f"(f[jp * 2 + 1])
                    : "l"(acc[r][jp]));
            float4* dst = reinterpret_cast<float4*>(&g_table[(size_t)v * QP + jb]);
            dst[0] = make_float4(f[0] + bv[0], f[1] + bv[1], f[2] + bv[2], f[3] + bv[3]);
            dst[1] = make_float4(f[4] + bv[4], f[5] + bv[5], f[6] + bv[6], f[7] + bv[7]);
        }
    }
}

// ---------------------------------------------------------------------------
// Scan: one block / batch row; 4-slot cp.async pipeline, one sync per iter.
// Packed rows: 768 floats; thread p reads its e(p) columns at base(p).
// ---------------------------------------------------------------------------
__global__ void __launch_bounds__(256) scan_kernel(const int* __restrict__ docs,
                                                   const int* __restrict__ doc_lens,
                                                   const int* __restrict__ end_states,
                                                   const float* __restrict__ wild,
                                                   const float* __restrict__ lin_w,
                                                   const float* __restrict__ lin_b,
                                                   float* __restrict__ out)
{
    __shared__ __align__(16) float buf[4][QP];
    __shared__ int   toks[TT];
    __shared__ float wsum[8];
    __shared__ float wsum2[2][8];
    __shared__ float s_mean;

    const int b   = blockIdx.x;
    const int tid = threadIdx.x;
    const int len = doc_lens[b];

    if (tid < TT) toks[tid] = docs[b * TT + tid];

    const bool act = tid < PP;
    float w0 = 0.f, w1 = 0.f, w2 = 0.f, w3 = 0.f, w4 = 0.f;
    int e = 2, base = 0;
    if (act) {
        w0 = wild[tid * 5 + 0];
        w1 = wild[tid * 5 + 1];
        w2 = wild[tid * 5 + 2];
        w3 = wild[tid * 5 + 3];
        w4 = wild[tid * 5 + 4];
        e  = end_states[tid];
        base = (tid < 50)  ? 2 * tid
             : (tid < 100) ? 100 + 3 * (tid - 50)
             : (tid < 150) ? 250 + 4 * (tid - 100)
                           : 450 + 5 * (tid - 150);
    }
    __syncthreads();

    const float NEG = __int_as_float(0xff800000);
    float h1 = NEG, h2 = NEG, h3 = NEG, h4 = NEG, h5 = NEG, sc = NEG;

    const uint32_t sbase = smem_u32(buf);

#pragma unroll
    for (int s = 0; s < 3; s++) {                  // len >= 8 > 3 always
        if (tid < 192) {
            const float* g = g_table + (size_t)toks[s] * QP + tid * 4;
            uint32_t dd = sbase + s * 3072 + tid * 16;
            asm volatile("cp.async.cg.shared.global [%0], [%1], 16;" :: "r"(dd), "l"(g));
        }
        asm volatile("cp.async.commit_group;");
    }

    for (int t = 0; t < len; t++) {
        asm volatile("cp.async.wait_group 2;");
        __syncthreads();
        int tn = t + 3;
        if (tn < len && tid < 192) {
            const float* g = g_table + (size_t)toks[tn] * QP + tid * 4;
            uint32_t dd = sbase + (tn & 3) * 3072 + tid * 16;
            asm volatile("cp.async.cg.shared.global [%0], [%1], 16;" :: "r"(dd), "l"(g));
        }
        asm volatile("cp.async.commit_group;");
        if (act) {
            const float* r = buf[t & 3] + base;
            float t0 = r[0];
            float t1 = r[1];
            float t2 = (e > 2) ? r[2] : NEG;
            float t3 = (e > 3) ? r[3] : NEG;
            float t4 = (e > 4) ? r[4] : NEG;
            float m0 = fmaxf(t0, w0);
            float m1 = fmaxf(t1, w1);
            float m2 = fmaxf(t2, w2);
            float m3 = fmaxf(t3, w3);
            float m4 = fmaxf(t4, w4);
            h5 = h4 + m4;          // uses OLD h4..h1
            h4 = h3 + m3;
            h3 = h2 + m2;
            h2 = h1 + m1;
            h1 = m0;
            float ev = (e == 2) ? h2 : (e == 3) ? h3 : (e == 4) ? h4 : h5;
            sc = fmaxf(sc, ev);
        }
    }

    // LN+binarize collapses to (sc > mean); then 2-wide linear
    const int lane = tid & 31, warp = tid >> 5;

    float x = act ? sc : 0.f;
#pragma unroll
    for (int o = 16; o; o >>= 1) x += __shfl_down_sync(0xffffffffu, x, o);
    if (lane == 0) wsum[warp] = x;
    __syncthreads();
    if (tid == 0) {
        float tot = 0.f;
#pragma unroll
        for (int i = 0; i < 8; i++) tot += wsum[i];
        s_mean = tot / 200.f;
    }
    __syncthreads();
    const float mean = s_mean;

    float c0 = 0.f, c1 = 0.f;
    if (act && sc > mean) {
        c0 = lin_w[tid];
        c1 = lin_w[PP + tid];
    }
#pragma unroll
    for (int o = 16; o; o >>= 1) {
        c0 += __shfl_down_sync(0xffffffffu, c0, o);
        c1 += __shfl_down_sync(0xffffffffu, c1, o);
    }
    if (lane == 0) { wsum2[0][warp] = c0; wsum2[1][warp] = c1; }
    __syncthreads();
    if (tid == 0) {
        float t0 = 0.f, t1 = 0.f;
#pragma unroll
        for (int i = 0; i < 8; i++) { t0 += wsum2[0][i]; t1 += wsum2[1][i]; }
        out[b * 2 + 0] = t0 + lin_b[0];
        out[b * 2 + 1] = t1 + lin_b[1];
    }
}

// ---------------------------------------------------------------------------
extern "C" void kernel_launch(void* const* d_in, const int* in_sizes, int n_in,
                              void* d_out, int out_size)
{
    const int*   docs       = (const int*)  d_in[0];
    const int*   doc_lens   = (const int*)  d_in[1];
    const int*   end_states = (const int*)  d_in[2];
    const float* emb        = (const float*)d_in[3];
    const float* diags      = (const float*)d_in[4];
    const float* bias       = (const float*)d_in[5];
    const float* wild       = (const float*)d_in[6];
    const float* lin_w      = (const float*)d_in[7];
    const float* lin_b      = (const float*)d_in[8];
    float* out = (float*)d_out;

    pack_kernel<<<(KPAD * QP + 255) / 256, 256>>>(diags, bias);
    gemm_kernel<<<dim3(JT, VT), 256>>>(emb);
    scan_kernel<<<BB, 256>>>(docs, doc_lens, end_states, wild, lin_w, lin_b, out);
}